// round 4
// baseline (speedup 1.0000x reference)
#include <cuda_runtime.h>
#include <cstdint>

#define SEQ    2048
#define BATCH  512
#define INPT   64
#define HIDDEN 128
#define BB     2               // batch per recurrence block
#define NBLK   (BATCH / BB)    // 256 blocks -> 2 per SM
#define NTHR   256

// 512MB scratch: xp[t][b][j] = xs[t][b] @ W_ih^T + (b_ih + b_hh)
__device__ float g_xp[(size_t)SEQ * BATCH * HIDDEN];

// ---- packed f32x2 helpers (sm_103a) ----
__device__ __forceinline__ unsigned long long ffma2(unsigned long long a,
                                                    unsigned long long b,
                                                    unsigned long long c) {
    unsigned long long d;
    asm("fma.rn.f32x2 %0, %1, %2, %3;" : "=l"(d) : "l"(a), "l"(b), "l"(c));
    return d;
}
__device__ __forceinline__ unsigned long long add2(unsigned long long a,
                                                   unsigned long long b) {
    unsigned long long d;
    asm("add.rn.f32x2 %0, %1, %2;" : "=l"(d) : "l"(a), "l"(b));
    return d;
}
__device__ __forceinline__ float lo_plus_hi(unsigned long long v) {
    float x, y;
    asm("mov.b64 {%0, %1}, %2;" : "=f"(x), "=f"(y) : "l"(v));
    return x + y;
}
__device__ __forceinline__ float tanh_fast(float z) {
    float az = fabsf(z);
    float e  = __expf(-2.0f * az);
    float r  = __fdividef(1.0f - e, 1.0f + e);
    return copysignf(r, z);
}
__device__ __forceinline__ void cp16(void* smem_dst, const float* gsrc) {
    unsigned dst = (unsigned)__cvta_generic_to_shared(smem_dst);
    asm volatile("cp.async.ca.shared.global [%0], [%1], 16;" :: "r"(dst), "l"(gsrc));
}

// ============================================================================
// Kernel 1: time-parallel x-projection GEMM. One block = 64 rows of X.
// xp[row][j] = sum_k xs[row][k]*W_ih[j][k] + b_ih[j] + b_hh[j]
// ============================================================================
#define XROWS 64
#define XBLK  ((SEQ * BATCH) / XROWS)   // 16384 blocks

__global__ void __launch_bounds__(256)
xproj_kernel(const float* __restrict__ xs,
             const float* __restrict__ W_ih,
             const float* __restrict__ b_ih,
             const float* __restrict__ b_hh) {
    __shared__ __align__(16) float xsh[XROWS][INPT];   // 16KB
    const int tid = threadIdx.x;
    const int j   = tid & (HIDDEN - 1);
    const int rh  = tid >> 7;                          // 0/1 row parity
    const long row0 = (long)blockIdx.x * XROWS;

    // full K=64 weight row in registers (32 f32x2 pairs)
    unsigned long long w[INPT / 2];
    const unsigned long long* wr =
        reinterpret_cast<const unsigned long long*>(W_ih + (size_t)j * INPT);
    #pragma unroll
    for (int i = 0; i < INPT / 2; i++) w[i] = wr[i];
    const float bias = b_ih[j] + b_hh[j];

    // stage 16KB of x: 1024 chunks of 16B, 4 per thread
    float* xf = &xsh[0][0];
    #pragma unroll
    for (int c = 0; c < 4; c++) {
        int idx = tid + 256 * c;
        cp16(xf + idx * 4, xs + row0 * INPT + idx * 4);
    }
    asm volatile("cp.async.commit_group;" ::);
    asm volatile("cp.async.wait_group 0;" ::);
    __syncthreads();

    for (int r = rh; r < XROWS; r += 2) {
        const ulonglong2* xr = reinterpret_cast<const ulonglong2*>(&xsh[r][0]);
        unsigned long long a0 = 0, a1 = 0, a2 = 0, a3 = 0;
        #pragma unroll
        for (int i = 0; i < 8; i++) {
            ulonglong2 q  = xr[2 * i];
            ulonglong2 q2 = xr[2 * i + 1];
            a0 = ffma2(w[4 * i],     q.x,  a0);
            a1 = ffma2(w[4 * i + 1], q.y,  a1);
            a2 = ffma2(w[4 * i + 2], q2.x, a2);
            a3 = ffma2(w[4 * i + 3], q2.y, a3);
        }
        float s = lo_plus_hi(add2(add2(a0, a1), add2(a2, a3)));
        g_xp[(row0 + r) * HIDDEN + j] = s + bias;
    }
}

// ============================================================================
// Kernel 2: serial recurrence.
// Thread slot: jp = wid*8+(lane&7) in [0,64), kq = lane>>3 in [0,4).
// Owns j0=jp, j1=jp+64, k-range [kq*32, kq*32+32), both batches.
// h smem layout v[buf][b][kq][36]: pads make all LDS/STS conflict-free.
// ============================================================================
__global__ void __launch_bounds__(NTHR, 2)
rnn_kernel(const float* __restrict__ W_hh,
           const float* __restrict__ W_out,
           const float* __restrict__ b_out,
           float* __restrict__ out) {
    __shared__ __align__(16) float v[2][BB][4][36];    // h double buffer
    __shared__ __align__(16) float xb[2][BB][HIDDEN];  // xp double buffer

    const int tid  = threadIdx.x;
    const int wid  = tid >> 5;
    const int lane = tid & 31;
    const int jp   = wid * 8 + (lane & 7);
    const int kq   = lane >> 3;
    const long bbase = (long)blockIdx.x * BB;

    // final-value assignment for this lane
    const int b_st = kq & 1;
    const int j_st = (kq >= 2) ? (jp + 64) : jp;

    // weights: rows j0=jp and j1=jp+64, k-quarter kq (16 pairs each)
    unsigned long long w0[16], w1[16];
    {
        const unsigned long long* r0 = reinterpret_cast<const unsigned long long*>(
            W_hh + (size_t)jp * HIDDEN + kq * 32);
        const unsigned long long* r1 = reinterpret_cast<const unsigned long long*>(
            W_hh + (size_t)(jp + 64) * HIDDEN + kq * 32);
        #pragma unroll
        for (int i = 0; i < 16; i++) { w0[i] = r0[i]; w1[i] = r1[i]; }
    }

    // init: zero h buffers; stage xp(0)
    for (int i = tid; i < 2 * BB * 4 * 36; i += NTHR)
        (&v[0][0][0][0])[i] = 0.0f;
    if (tid < 64) {
        int b = tid >> 5, seg = tid & 31;
        cp16(&xb[0][b][seg * 4], g_xp + (bbase + b) * HIDDEN + seg * 4);
    }
    asm volatile("cp.async.commit_group;" ::);
    asm volatile("cp.async.wait_group 0;" ::);
    __syncthreads();

    auto step = [&](int cur, int t) {
        const int nxt = cur ^ 1;

        // xb value for this lane's final (j,b) — load early, hide latency
        const float xbv = xb[cur][b_st][j_st];

        // prefetch xp(t+1)
        if (t + 1 < SEQ && tid < 64) {
            int b = tid >> 5, seg = tid & 31;
            cp16(&xb[nxt][b][seg * 4],
                 g_xp + ((long)(t + 1) * BATCH + bbase + b) * HIDDEN + seg * 4);
        }
        asm volatile("cp.async.commit_group;" ::);

        // accumulate: 8 LDS.128 + 32 FMA2 per batch
        unsigned long long a00 = 0, a01 = 0, a10 = 0, a11 = 0;  // b0: j0, j1
        unsigned long long a20 = 0, a21 = 0, a30 = 0, a31 = 0;  // b1: j0, j1
        {
            const ulonglong2* hp = reinterpret_cast<const ulonglong2*>(&v[cur][0][kq][0]);
            #pragma unroll
            for (int i = 0; i < 4; i++) {
                ulonglong2 q  = hp[2 * i];
                ulonglong2 q2 = hp[2 * i + 1];
                a00 = ffma2(w0[4 * i],     q.x,  a00);
                a10 = ffma2(w1[4 * i],     q.x,  a10);
                a01 = ffma2(w0[4 * i + 1], q.y,  a01);
                a11 = ffma2(w1[4 * i + 1], q.y,  a11);
                a00 = ffma2(w0[4 * i + 2], q2.x, a00);
                a10 = ffma2(w1[4 * i + 2], q2.x, a10);
                a01 = ffma2(w0[4 * i + 3], q2.y, a01);
                a11 = ffma2(w1[4 * i + 3], q2.y, a11);
            }
        }
        {
            const ulonglong2* hp = reinterpret_cast<const ulonglong2*>(&v[cur][1][kq][0]);
            #pragma unroll
            for (int i = 0; i < 4; i++) {
                ulonglong2 q  = hp[2 * i];
                ulonglong2 q2 = hp[2 * i + 1];
                a20 = ffma2(w0[4 * i],     q.x,  a20);
                a30 = ffma2(w1[4 * i],     q.x,  a30);
                a21 = ffma2(w0[4 * i + 1], q.y,  a21);
                a31 = ffma2(w1[4 * i + 1], q.y,  a31);
                a20 = ffma2(w0[4 * i + 2], q2.x, a20);
                a30 = ffma2(w1[4 * i + 2], q2.x, a30);
                a21 = ffma2(w0[4 * i + 3], q2.y, a21);
                a31 = ffma2(w1[4 * i + 3], q2.y, a31);
            }
        }
        float s00 = lo_plus_hi(add2(a00, a01));  // (j0, b0) partial over kq
        float s10 = lo_plus_hi(add2(a10, a11));  // (j1, b0)
        float s01 = lo_plus_hi(add2(a20, a21));  // (j0, b1)
        float s11 = lo_plus_hi(add2(a30, a31));  // (j1, b1)

        // Round A (xor 8): even kq keeps b0, odd keeps b1
        const bool oddq = (kq & 1);
        float sendA0 = oddq ? s00 : s01;
        float sendA1 = oddq ? s10 : s11;
        float rA0 = __shfl_xor_sync(0xffffffffu, sendA0, 8);
        float rA1 = __shfl_xor_sync(0xffffffffu, sendA1, 8);
        float S0 = (oddq ? s01 : s00) + rA0;   // (j0, b_st) over kq-pair
        float S1 = (oddq ? s11 : s10) + rA1;   // (j1, b_st)

        // Round B (xor 16): kq<2 keeps j0, kq>=2 keeps j1
        const bool hiq = (kq >= 2);
        float sendB = hiq ? S0 : S1;
        float rB = __shfl_xor_sync(0xffffffffu, sendB, 16);
        float z = (hiq ? S1 : S0) + rB + xbv;

        v[nxt][b_st][j_st >> 5][j_st & 31] = tanh_fast(z);

        asm volatile("cp.async.wait_group 0;" ::);
        __syncthreads();
    };

    for (int t = 0; t < SEQ; t += 2) {
        step(0, t);
        step(1, t + 1);
    }

    // output projection: out[b] = h_final[b] . W_out + b_out (final in buf 0)
    if (tid < BB * 32) {
        int b = tid >> 5, l = tid & 31;
        float s = 0.0f;
        #pragma unroll
        for (int m = 0; m < 4; m++) {
            int jj = l + 32 * m;
            s += v[0][b][jj >> 5][jj & 31] * W_out[jj];
        }
        #pragma unroll
        for (int off = 16; off; off >>= 1)
            s += __shfl_down_sync(0xffffffffu, s, off);
        if (l == 0) out[bbase + b] = s + b_out[0];
    }
}

extern "C" void kernel_launch(void* const* d_in, const int* in_sizes, int n_in,
                              void* d_out, int out_size) {
    const float* xs    = (const float*)d_in[0];
    const float* W_ih  = (const float*)d_in[1];
    const float* W_hh  = (const float*)d_in[2];
    const float* b_ih  = (const float*)d_in[3];
    const float* b_hh  = (const float*)d_in[4];
    const float* W_out = (const float*)d_in[5];
    const float* b_out = (const float*)d_in[6];

    xproj_kernel<<<XBLK, 256>>>(xs, W_ih, b_ih, b_hh);
    rnn_kernel<<<NBLK, NTHR>>>(W_hh, W_out, b_out, (float*)d_out);
}

// round 5
// speedup vs baseline: 1.1511x; 1.1511x over previous
#include <cuda_runtime.h>
#include <cstdint>

#define SEQ    2048
#define BATCH  512
#define INPT   64
#define HIDDEN 128
#define KTOT   192             // combined [x ; h] reduction dim
#define KH     96              // per-thread k half
#define BB     2               // batch per block
#define NBLK   (BATCH / BB)    // 256 blocks -> 2 per SM
#define NTHR   256
#define VPAD   100             // 96 k + 4 pad floats per (b, kh) region

// ---- packed f32x2 helpers (sm_103a) ----
__device__ __forceinline__ unsigned long long ffma2(unsigned long long a,
                                                    unsigned long long b,
                                                    unsigned long long c) {
    unsigned long long d;
    asm("fma.rn.f32x2 %0, %1, %2, %3;" : "=l"(d) : "l"(a), "l"(b), "l"(c));
    return d;
}
__device__ __forceinline__ unsigned long long add2(unsigned long long a,
                                                   unsigned long long b) {
    unsigned long long d;
    asm("add.rn.f32x2 %0, %1, %2;" : "=l"(d) : "l"(a), "l"(b));
    return d;
}
__device__ __forceinline__ unsigned long long pack2(float lo, float hi) {
    unsigned long long v;
    asm("mov.b64 %0, {%1, %2};" : "=l"(v) : "f"(lo), "f"(hi));
    return v;
}
__device__ __forceinline__ float lo_plus_hi(unsigned long long v) {
    float x, y;
    asm("mov.b64 {%0, %1}, %2;" : "=f"(x), "=f"(y) : "l"(v));
    return x + y;
}
__device__ __forceinline__ float tanh_fast(float z) {
    float az = fabsf(z);
    float e  = __expf(-2.0f * az);
    float r  = __fdividef(1.0f - e, 1.0f + e);
    return copysignf(r, z);
}
__device__ __forceinline__ void cp16(void* smem_dst, const float* gsrc) {
    unsigned dst = (unsigned)__cvta_generic_to_shared(smem_dst);
    asm volatile("cp.async.ca.shared.global [%0], [%1], 16;" :: "r"(dst), "l"(gsrc));
}

// ============================================================================
// Fused kernel: serial recurrence over K=192 combined [x ; h] vector.
// Thread slot: j = wid*16 + (lane&15) in [0,128), kh = lane>>4 in {0,1}.
// Thread owns k range [kh*96, kh*96+96) of the combined vector, both batches.
// smem v[buf][b][kh][100]: regions 400B apart -> distinct bank quads.
// combined index c: c<96 -> v[.][b][0][c]; c>=96 -> v[.][b][1][c-96].
//   x(t)[i] lives at c=i (i<64); h(t)[j] lives at c=64+j.
// ============================================================================
__global__ void __launch_bounds__(NTHR, 2)
rnn_fused_kernel(const float* __restrict__ xs,
                 const float* __restrict__ W_ih,
                 const float* __restrict__ W_hh,
                 const float* __restrict__ b_ih,
                 const float* __restrict__ b_hh,
                 const float* __restrict__ W_out,
                 const float* __restrict__ b_out,
                 float* __restrict__ out) {
    __shared__ __align__(16) float v[2][BB][2][VPAD];

    const int tid  = threadIdx.x;
    const int wid  = tid >> 5;
    const int lane = tid & 31;
    const int j    = wid * 16 + (lane & 15);
    const int kh   = lane >> 4;
    const int k0   = kh * KH;
    const long bbase = (long)blockIdx.x * BB;

    // Combined weight row [W_ih[j] | W_hh[j]], this thread's 96-k slice,
    // packed as 48 f32x2 pairs (96 regs). Pairs never straddle the 64-boundary.
    unsigned long long w[KH / 2];
    #pragma unroll
    for (int i = 0; i < KH / 2; i++) {
        int ka = k0 + 2 * i;
        int kb = ka + 1;
        float wa = (ka < INPT) ? W_ih[j * INPT + ka] : W_hh[j * HIDDEN + (ka - INPT)];
        float wb = (kb < INPT) ? W_ih[j * INPT + kb] : W_hh[j * HIDDEN + (kb - INPT)];
        w[i] = pack2(wa, wb);
    }
    const float bias = b_ih[j] + b_hh[j];

    // h-store slot for this thread: batch kh, combined index 64+j
    const int st_r   = (j >= 32);                    // region
    const int st_idx = st_r ? (j - 32) : (64 + j);   // index within region

    // init: zero everything (h0 = 0), stage x(0)
    for (int i = tid; i < 2 * BB * 2 * VPAD; i += NTHR)
        (&v[0][0][0][0])[i] = 0.0f;
    __syncthreads();
    if (tid < 32) {
        int b = tid >> 4, seg = tid & 15;
        cp16(&v[0][b][0][seg * 4], xs + (bbase + b) * INPT + seg * 4);
    }
    asm volatile("cp.async.commit_group;" ::);
    asm volatile("cp.async.wait_group 0;" ::);
    __syncthreads();

    auto step = [&](int cur, int t) {
        const int nxt = cur ^ 1;

        // prefetch raw x(t+1) into the x-region of the next buffer
        if (t + 1 < SEQ && tid < 32) {
            int b = tid >> 4, seg = tid & 15;
            cp16(&v[nxt][b][0][seg * 4],
                 xs + ((long)(t + 1) * BATCH + bbase + b) * INPT + seg * 4);
        }
        asm volatile("cp.async.commit_group;" ::);

        // dot products over this thread's 96-k slice, both batches
        float s[BB];
        #pragma unroll
        for (int b = 0; b < BB; b++) {
            const ulonglong2* hp =
                reinterpret_cast<const ulonglong2*>(&v[cur][b][kh][0]);
            unsigned long long a0 = 0, a1 = 0;
            #pragma unroll
            for (int i = 0; i < 12; i++) {     // 24 LDS.128, 48 FMA2 per b? no: 12*4=48 pairs/2... 
                ulonglong2 q  = hp[2 * i];
                ulonglong2 q2 = hp[2 * i + 1];
                a0 = ffma2(w[4 * i],     q.x,  a0);
                a1 = ffma2(w[4 * i + 1], q.y,  a1);
                a0 = ffma2(w[4 * i + 2], q2.x, a0);
                a1 = ffma2(w[4 * i + 3], q2.y, a1);
            }
            s[b] = lo_plus_hi(add2(a0, a1));
        }

        // combine k-halves: lane L and L^16 share the same j
        float z0 = s[0] + __shfl_xor_sync(0xffffffffu, s[0], 16);
        float z1 = s[1] + __shfl_xor_sync(0xffffffffu, s[1], 16);
        float z  = (kh ? z1 : z0) + bias;

        // each thread stores h(t+1) for (j, b = kh)
        v[nxt][kh][st_r][st_idx] = tanh_fast(z);

        asm volatile("cp.async.wait_group 0;" ::);
        __syncthreads();
    };

    for (int t = 0; t < SEQ; t += 2) {
        step(0, t);
        step(1, t + 1);
    }

    // output projection: out[b] = h_final[b] . W_out + b_out  (final in buf 0)
    if (tid < BB * 32) {
        int b = tid >> 5, l = tid & 31;
        float sacc = 0.0f;
        #pragma unroll
        for (int m = 0; m < 4; m++) {
            int jj = l + 32 * m;
            int c  = 64 + jj;
            float hv = (c < 96) ? v[0][b][0][c] : v[0][b][1][c - 96];
            sacc += hv * W_out[jj];
        }
        #pragma unroll
        for (int off = 16; off; off >>= 1)
            sacc += __shfl_down_sync(0xffffffffu, sacc, off);
        if (l == 0) out[bbase + b] = sacc + b_out[0];
    }
}

extern "C" void kernel_launch(void* const* d_in, const int* in_sizes, int n_in,
                              void* d_out, int out_size) {
    const float* xs    = (const float*)d_in[0];
    const float* W_ih  = (const float*)d_in[1];
    const float* W_hh  = (const float*)d_in[2];
    const float* b_ih  = (const float*)d_in[3];
    const float* b_hh  = (const float*)d_in[4];
    const float* W_out = (const float*)d_in[5];
    const float* b_out = (const float*)d_in[6];

    rnn_fused_kernel<<<NBLK, NTHR>>>(xs, W_ih, W_hh, b_ih, b_hh, W_out, b_out,
                                     (float*)d_out);
}

// round 6
// speedup vs baseline: 1.3623x; 1.1835x over previous
#include <cuda_runtime.h>
#include <cstdint>

#define SEQ    2048
#define BATCH  512
#define INPT   64
#define HIDDEN 128
#define KTOT   192             // combined [x ; h] reduction dim
#define KQ     48              // per-thread k quarter
#define NQ     4
#define BB     2               // batch per block
#define NBLK   (BATCH / BB)    // 256 blocks -> 2 per SM
#define NTHR   256
#define VQ     52              // 48 k + 4 pad floats per (b, kq) region

// ---- packed f32x2 helpers (sm_103a) ----
__device__ __forceinline__ unsigned long long ffma2(unsigned long long a,
                                                    unsigned long long b,
                                                    unsigned long long c) {
    unsigned long long d;
    asm("fma.rn.f32x2 %0, %1, %2, %3;" : "=l"(d) : "l"(a), "l"(b), "l"(c));
    return d;
}
__device__ __forceinline__ unsigned long long add2(unsigned long long a,
                                                   unsigned long long b) {
    unsigned long long d;
    asm("add.rn.f32x2 %0, %1, %2;" : "=l"(d) : "l"(a), "l"(b));
    return d;
}
__device__ __forceinline__ unsigned long long pack2(float lo, float hi) {
    unsigned long long v;
    asm("mov.b64 %0, {%1, %2};" : "=l"(v) : "f"(lo), "f"(hi));
    return v;
}
__device__ __forceinline__ float lo_plus_hi(unsigned long long v) {
    float x, y;
    asm("mov.b64 {%0, %1}, %2;" : "=f"(x), "=f"(y) : "l"(v));
    return x + y;
}
__device__ __forceinline__ float tanh_fast(float z) {
    float az = fabsf(z);
    float e  = __expf(-2.0f * az);
    float r  = __fdividef(1.0f - e, 1.0f + e);
    return copysignf(r, z);
}
__device__ __forceinline__ void cp16(void* smem_dst, const float* gsrc) {
    unsigned dst = (unsigned)__cvta_generic_to_shared(smem_dst);
    asm volatile("cp.async.ca.shared.global [%0], [%1], 16;" :: "r"(dst), "l"(gsrc));
}

// Combined weight element: c<64 -> W_ih[j][c], c>=64 -> W_hh[j][c-64]
__device__ __forceinline__ float wcomb(const float* W_ih, const float* W_hh,
                                       int j, int c) {
    return (c < INPT) ? W_ih[j * INPT + c] : W_hh[j * HIDDEN + (c - INPT)];
}

// ============================================================================
// Fused recurrence. Combined vector u(t) = [x(t) (64) ; h(t) (128)], K=192.
// smem: v[buf][b][kq][52], region kq holds combined idx [kq*48, kq*48+48).
// Thread (jp = wid*8 + (lane&7), kq = lane>>3) owns rows jp and jp+64,
// k-quarter kq, both batches. 24 LDS.128 + 96 FMA2 per thread per step.
// ============================================================================
__global__ void __launch_bounds__(NTHR, 2)
rnn_fused_kernel(const float* __restrict__ xs,
                 const float* __restrict__ W_ih,
                 const float* __restrict__ W_hh,
                 const float* __restrict__ b_ih,
                 const float* __restrict__ b_hh,
                 const float* __restrict__ W_out,
                 const float* __restrict__ b_out,
                 float* __restrict__ out) {
    __shared__ __align__(16) float v[2][BB][NQ][VQ];

    const int tid  = threadIdx.x;
    const int wid  = tid >> 5;
    const int lane = tid & 31;
    const int jp   = wid * 8 + (lane & 7);
    const int kq   = lane >> 3;
    const long bbase = (long)blockIdx.x * BB;

    // final-value slot for this lane (round-4 reduction layout)
    const int b_st = kq & 1;
    const int j_st = (kq >= 2) ? (jp + 64) : jp;
    const int c_st = INPT + j_st;            // combined index of h[j_st]
    const int st_r = c_st / KQ;              // region (1..3)
    const int st_i = c_st % KQ;

    // weights: rows jp and jp+64, combined k-slice [kq*48, kq*48+48)
    unsigned long long w0[KQ / 2], w1[KQ / 2];
    #pragma unroll
    for (int i = 0; i < KQ / 2; i++) {
        int ca = kq * KQ + 2 * i;
        w0[i] = pack2(wcomb(W_ih, W_hh, jp,      ca),
                      wcomb(W_ih, W_hh, jp,      ca + 1));
        w1[i] = pack2(wcomb(W_ih, W_hh, jp + 64, ca),
                      wcomb(W_ih, W_hh, jp + 64, ca + 1));
    }
    const float bias = b_ih[j_st] + b_hh[j_st];

    // init: zero (h0 = 0), stage x(0). 16B chunk seg of batch b:
    // seg<12 -> region 0 idx seg*4 ; seg>=12 -> region 1 idx (seg-12)*4
    for (int i = tid; i < 2 * BB * NQ * VQ; i += NTHR)
        (&v[0][0][0][0])[i] = 0.0f;
    __syncthreads();
    if (tid < 32) {
        int b = tid >> 4, seg = tid & 15;
        float* dst = (seg < 12) ? &v[0][b][0][seg * 4]
                                : &v[0][b][1][(seg - 12) * 4];
        cp16(dst, xs + (bbase + b) * INPT + seg * 4);
    }
    asm volatile("cp.async.commit_group;" ::);
    asm volatile("cp.async.wait_group 0;" ::);
    __syncthreads();

    auto step = [&](int cur, int t) {
        const int nxt = cur ^ 1;

        // prefetch raw x(t+1) into next buffer's x region
        if (t + 1 < SEQ && tid < 32) {
            int b = tid >> 4, seg = tid & 15;
            float* dst = (seg < 12) ? &v[nxt][b][0][seg * 4]
                                    : &v[nxt][b][1][(seg - 12) * 4];
            cp16(dst, xs + ((long)(t + 1) * BATCH + bbase + b) * INPT + seg * 4);
        }
        asm volatile("cp.async.commit_group;" ::);

        // 24 LDS.128, each feeding 2 j-rows: 96 FMA2 total
        const ulonglong2* h0 = reinterpret_cast<const ulonglong2*>(&v[cur][0][kq][0]);
        const ulonglong2* h1 = reinterpret_cast<const ulonglong2*>(&v[cur][1][kq][0]);
        unsigned long long a00 = 0, a01 = 0, a10 = 0, a11 = 0;  // b0: j0,j1
        unsigned long long a20 = 0, a21 = 0, a30 = 0, a31 = 0;  // b1: j0,j1
        #pragma unroll
        for (int i = 0; i < 6; i++) {   // 4 pairs (2 ulonglong2) per iter per b
            ulonglong2 p  = h0[2 * i];
            ulonglong2 p2 = h0[2 * i + 1];
            ulonglong2 q  = h1[2 * i];
            ulonglong2 q2 = h1[2 * i + 1];
            a00 = ffma2(w0[4 * i],     p.x,  a00);
            a10 = ffma2(w1[4 * i],     p.x,  a10);
            a01 = ffma2(w0[4 * i + 1], p.y,  a01);
            a11 = ffma2(w1[4 * i + 1], p.y,  a11);
            a00 = ffma2(w0[4 * i + 2], p2.x, a00);
            a10 = ffma2(w1[4 * i + 2], p2.x, a10);
            a01 = ffma2(w0[4 * i + 3], p2.y, a01);
            a11 = ffma2(w1[4 * i + 3], p2.y, a11);
            a20 = ffma2(w0[4 * i],     q.x,  a20);
            a30 = ffma2(w1[4 * i],     q.x,  a30);
            a21 = ffma2(w0[4 * i + 1], q.y,  a21);
            a31 = ffma2(w1[4 * i + 1], q.y,  a31);
            a20 = ffma2(w0[4 * i + 2], q2.x, a20);
            a30 = ffma2(w1[4 * i + 2], q2.x, a30);
            a21 = ffma2(w0[4 * i + 3], q2.y, a21);
            a31 = ffma2(w1[4 * i + 3], q2.y, a31);
        }
        float s00 = lo_plus_hi(add2(a00, a01));  // (j0, b0) over kq
        float s10 = lo_plus_hi(add2(a10, a11));  // (j1, b0)
        float s01 = lo_plus_hi(add2(a20, a21));  // (j0, b1)
        float s11 = lo_plus_hi(add2(a30, a31));  // (j1, b1)

        // Round A (xor 8, kq pairs {0,1},{2,3}): even kq keeps b0, odd keeps b1
        const bool oddq = (kq & 1);
        float sendA0 = oddq ? s00 : s01;
        float sendA1 = oddq ? s10 : s11;
        float rA0 = __shfl_xor_sync(0xffffffffu, sendA0, 8);
        float rA1 = __shfl_xor_sync(0xffffffffu, sendA1, 8);
        float S0 = (oddq ? s01 : s00) + rA0;   // (j0, b_st) over k-half
        float S1 = (oddq ? s11 : s10) + rA1;   // (j1, b_st)

        // Round B (xor 16, other k-half): kq<2 keeps j0, kq>=2 keeps j1
        const bool hiq = (kq >= 2);
        float sendB = hiq ? S0 : S1;
        float rB = __shfl_xor_sync(0xffffffffu, sendB, 16);
        float z = (hiq ? S1 : S0) + rB + bias;

        v[nxt][b_st][st_r][st_i] = tanh_fast(z);

        asm volatile("cp.async.wait_group 0;" ::);
        __syncthreads();
    };

    for (int t = 0; t < SEQ; t += 2) {
        step(0, t);
        step(1, t + 1);
    }

    // output projection: out[b] = h_final[b] . W_out + b_out  (final in buf 0)
    if (tid < BB * 32) {
        int b = tid >> 5, l = tid & 31;
        float sacc = 0.0f;
        #pragma unroll
        for (int m = 0; m < 4; m++) {
            int jj = l + 32 * m;
            int c  = INPT + jj;
            sacc += v[0][b][c / KQ][c % KQ] * W_out[jj];
        }
        #pragma unroll
        for (int off = 16; off; off >>= 1)
            sacc += __shfl_down_sync(0xffffffffu, sacc, off);
        if (l == 0) out[bbase + b] = sacc + b_out[0];
    }
}

extern "C" void kernel_launch(void* const* d_in, const int* in_sizes, int n_in,
                              void* d_out, int out_size) {
    const float* xs    = (const float*)d_in[0];
    const float* W_ih  = (const float*)d_in[1];
    const float* W_hh  = (const float*)d_in[2];
    const float* b_ih  = (const float*)d_in[3];
    const float* b_hh  = (const float*)d_in[4];
    const float* W_out = (const float*)d_in[5];
    const float* b_out = (const float*)d_in[6];

    rnn_fused_kernel<<<NBLK, NTHR>>>(xs, W_ih, W_hh, b_ih, b_hh, W_out, b_out,
                                     (float*)d_out);
}

// round 7
// speedup vs baseline: 1.3983x; 1.0265x over previous
#include <cuda_runtime.h>
#include <cstdint>

#define SEQ    2048
#define BATCH  512
#define INPT   64
#define HIDDEN 128
#define KTOT   192             // combined [x ; h] reduction dim
#define KQ     48              // per-thread k quarter
#define BB     4               // batch per block
#define NBLK   (BATCH / BB)    // 128 blocks -> 1 per SM
#define NTHR   512
#define BSTR   216             // per-batch region stride (words), 216 % 32 = 24

// ---- packed f32x2 helpers (sm_103a) ----
__device__ __forceinline__ unsigned long long ffma2(unsigned long long a,
                                                    unsigned long long b,
                                                    unsigned long long c) {
    unsigned long long d;
    asm("fma.rn.f32x2 %0, %1, %2, %3;" : "=l"(d) : "l"(a), "l"(b), "l"(c));
    return d;
}
__device__ __forceinline__ unsigned long long add2(unsigned long long a,
                                                   unsigned long long b) {
    unsigned long long d;
    asm("add.rn.f32x2 %0, %1, %2;" : "=l"(d) : "l"(a), "l"(b));
    return d;
}
__device__ __forceinline__ unsigned long long pack2(float lo, float hi) {
    unsigned long long v;
    asm("mov.b64 %0, {%1, %2};" : "=l"(v) : "f"(lo), "f"(hi));
    return v;
}
__device__ __forceinline__ float lo_plus_hi(unsigned long long v) {
    float x, y;
    asm("mov.b64 {%0, %1}, %2;" : "=f"(x), "=f"(y) : "l"(v));
    return x + y;
}
__device__ __forceinline__ float tanh_fast(float z) {
    float az = fabsf(z);
    float e  = __expf(-2.0f * az);
    float r  = __fdividef(1.0f - e, 1.0f + e);
    return copysignf(r, z);
}
__device__ __forceinline__ void cp16(void* smem_dst, const float* gsrc) {
    unsigned dst = (unsigned)__cvta_generic_to_shared(smem_dst);
    asm volatile("cp.async.ca.shared.global [%0], [%1], 16;" :: "r"(dst), "l"(gsrc));
}

// Combined weight element: c<64 -> W_ih[j][c], c>=64 -> W_hh[j][c-64]
__device__ __forceinline__ float wcomb(const float* W_ih, const float* W_hh,
                                       int j, int c) {
    return (c < INPT) ? W_ih[j * INPT + c] : W_hh[j * HIDDEN + (c - INPT)];
}

// ============================================================================
// Fused recurrence, 1 block/SM. Combined u(t) = [x(t)(64) ; h(t)(128)], K=192.
// smem v[3][BB][216]: triple-buffered; combined index c lives in region
// kq = c/48 at word kq*52 + c%48 (regions padded to 52 words).
// Thread (jp = wid*4+(lane&3), kq = (lane>>2)&3, bh = lane>>4):
//   rows jp, jp+64; k-slice [kq*48, kq*48+48); batches 2bh, 2bh+1.
// 24 LDS.128 (conflict-free) + 96 FMA2 per thread per step.
// x prefetched TWO steps ahead (wait_group 1 -> never blocks).
// ============================================================================
__global__ void __launch_bounds__(NTHR, 1)
rnn_fused_kernel(const float* __restrict__ xs,
                 const float* __restrict__ W_ih,
                 const float* __restrict__ W_hh,
                 const float* __restrict__ b_ih,
                 const float* __restrict__ b_hh,
                 const float* __restrict__ W_out,
                 const float* __restrict__ b_out,
                 float* __restrict__ out) {
    __shared__ __align__(16) float v[3][BB][BSTR];

    const int tid  = threadIdx.x;
    const int wid  = tid >> 5;
    const int lane = tid & 31;
    const int jp   = wid * 4 + (lane & 3);
    const int kq   = (lane >> 2) & 3;
    const int bh   = lane >> 4;
    const long bbase = (long)blockIdx.x * BB;

    // final-value slot for this lane
    const int pe   = kq & 1;                 // row select
    const int ph   = (kq >> 1) & 1;          // batch select
    const int j_st = pe ? (jp + 64) : jp;
    const int b_st = 2 * bh + ph;
    const int c_st = INPT + j_st;
    const int st_off = b_st * BSTR + (c_st / KQ) * 52 + (c_st % KQ);

    // weights: rows jp and jp+64, combined k-slice [kq*48, kq*48+48)
    unsigned long long w0[KQ / 2], w1[KQ / 2];
    #pragma unroll
    for (int i = 0; i < KQ / 2; i++) {
        int ca = kq * KQ + 2 * i;
        w0[i] = pack2(wcomb(W_ih, W_hh, jp,      ca),
                      wcomb(W_ih, W_hh, jp,      ca + 1));
        w1[i] = pack2(wcomb(W_ih, W_hh, jp + 64, ca),
                      wcomb(W_ih, W_hh, jp + 64, ca + 1));
    }
    const float bias = b_ih[j_st] + b_hh[j_st];

    // x chunk mapping: 16B seg of batch b -> region0 idx seg*4 (seg<12)
    //                                      | region1 idx (seg-12)*4 (seg>=12)
    auto xdst = [&](int p, int b, int seg) -> float* {
        int off = (seg < 12) ? (seg * 4) : (52 + (seg - 12) * 4);
        return &v[p][b][off];
    };

    // init: zero buffer 0 h-region (h0 = 0); stage x(0) -> v[0], x(1) -> v[1]
    for (int i = tid; i < 3 * BB * BSTR; i += NTHR)
        (&v[0][0][0])[i] = 0.0f;
    __syncthreads();
    if (tid < BB * 16) {
        int b = tid >> 4, seg = tid & 15;
        cp16(xdst(0, b, seg), xs + (bbase + b) * INPT + seg * 4);
        cp16(xdst(1, b, seg), xs + ((long)BATCH + bbase + b) * INPT + seg * 4);
    }
    asm volatile("cp.async.commit_group;" ::);
    asm volatile("cp.async.wait_group 0;" ::);
    __syncthreads();

    const int b0 = 2 * bh, b1 = 2 * bh + 1;

    auto step = [&](int p0, int p1, int p2, int t) {
        // prefetch x(t+2) into buffer p2 (its readers finished last step)
        if (t + 2 < SEQ && tid < BB * 16) {
            int b = tid >> 4, seg = tid & 15;
            cp16(xdst(p2, b, seg),
                 xs + ((long)(t + 2) * BATCH + bbase + b) * INPT + seg * 4);
        }
        asm volatile("cp.async.commit_group;" ::);

        // 24 LDS.128, each feeding 2 j-rows
        const ulonglong2* h0 =
            reinterpret_cast<const ulonglong2*>(&v[p0][b0][kq * 52]);
        const ulonglong2* h1 =
            reinterpret_cast<const ulonglong2*>(&v[p0][b1][kq * 52]);
        unsigned long long a00 = 0, a01 = 0, a10 = 0, a11 = 0;  // b0: j0,j1
        unsigned long long a20 = 0, a21 = 0, a30 = 0, a31 = 0;  // b1: j0,j1
        #pragma unroll
        for (int i = 0; i < 6; i++) {
            ulonglong2 p  = h0[2 * i];
            ulonglong2 p2 = h0[2 * i + 1];
            ulonglong2 q  = h1[2 * i];
            ulonglong2 q2 = h1[2 * i + 1];
            a00 = ffma2(w0[4 * i],     p.x,  a00);
            a10 = ffma2(w1[4 * i],     p.x,  a10);
            a01 = ffma2(w0[4 * i + 1], p.y,  a01);
            a11 = ffma2(w1[4 * i + 1], p.y,  a11);
            a00 = ffma2(w0[4 * i + 2], p2.x, a00);
            a10 = ffma2(w1[4 * i + 2], p2.x, a10);
            a01 = ffma2(w0[4 * i + 3], p2.y, a01);
            a11 = ffma2(w1[4 * i + 3], p2.y, a11);
            a20 = ffma2(w0[4 * i],     q.x,  a20);
            a30 = ffma2(w1[4 * i],     q.x,  a30);
            a21 = ffma2(w0[4 * i + 1], q.y,  a21);
            a31 = ffma2(w1[4 * i + 1], q.y,  a31);
            a20 = ffma2(w0[4 * i + 2], q2.x, a20);
            a30 = ffma2(w1[4 * i + 2], q2.x, a30);
            a21 = ffma2(w0[4 * i + 3], q2.y, a21);
            a31 = ffma2(w1[4 * i + 3], q2.y, a31);
        }
        float s00 = lo_plus_hi(add2(a00, a01));  // (jp,    b0) over kq
        float s10 = lo_plus_hi(add2(a10, a11));  // (jp+64, b0)
        float s01 = lo_plus_hi(add2(a20, a21));  // (jp,    b1)
        float s11 = lo_plus_hi(add2(a30, a31));  // (jp+64, b1)

        // Round A (xor 4): even kq keeps row jp, odd keeps jp+64
        float sendA0 = pe ? s00 : s10;
        float sendA1 = pe ? s01 : s11;
        float rA0 = __shfl_xor_sync(0xffffffffu, sendA0, 4);
        float rA1 = __shfl_xor_sync(0xffffffffu, sendA1, 4);
        float S0 = (pe ? s10 : s00) + rA0;   // (j_st, b0) over kq-pair
        float S1 = (pe ? s11 : s01) + rA1;   // (j_st, b1)

        // Round B (xor 8): kq<2 keeps b0, kq>=2 keeps b1
        float sendB = ph ? S0 : S1;
        float rB = __shfl_xor_sync(0xffffffffu, sendB, 8);
        float z = (ph ? S1 : S0) + rB + bias;

        v[p1][0][st_off] = tanh_fast(z);     // [0] folded into st_off

        asm volatile("cp.async.wait_group 1;" ::);  // x(t+1) (committed last step)
        __syncthreads();
    };

    // 2046 steps in rotations of 3, then 2 tail steps. Final h in v[2].
    for (int t = 0; t < SEQ - 2; t += 3) {
        step(0, 1, 2, t);
        step(1, 2, 0, t + 1);
        step(2, 0, 1, t + 2);
    }
    step(0, 1, 2, SEQ - 2);
    step(1, 2, 0, SEQ - 1);

    // output projection: out[b] = h_final[b] . W_out + b_out  (h in v[2])
    if (tid < BB * 32) {
        int b = tid >> 5, l = tid & 31;
        float sacc = 0.0f;
        #pragma unroll
        for (int m = 0; m < 4; m++) {
            int jj = l + 32 * m;
            int c  = INPT + jj;
            sacc += v[2][b][(c / KQ) * 52 + (c % KQ)] * W_out[jj];
        }
        #pragma unroll
        for (int off = 16; off; off >>= 1)
            sacc += __shfl_down_sync(0xffffffffu, sacc, off);
        if (l == 0) out[bbase + b] = sacc + b_out[0];
    }
}

extern "C" void kernel_launch(void* const* d_in, const int* in_sizes, int n_in,
                              void* d_out, int out_size) {
    const float* xs    = (const float*)d_in[0];
    const float* W_ih  = (const float*)d_in[1];
    const float* W_hh  = (const float*)d_in[2];
    const float* b_ih  = (const float*)d_in[3];
    const float* b_hh  = (const float*)d_in[4];
    const float* W_out = (const float*)d_in[5];
    const float* b_out = (const float*)d_in[6];

    rnn_fused_kernel<<<NBLK, NTHR>>>(xs, W_ih, W_hh, b_ih, b_hh, W_out, b_out,
                                     (float*)d_out);
}